// round 14
// baseline (speedup 1.0000x reference)
#include <cuda_runtime.h>
#include <cuda_fp16.h>
#include <math.h>
#include <stdint.h>

#define HIDDEN 768
#define KEY    128
#define INTER  1536
#define BDIM   4
#define SEQ    2048
#define M_TOT  (BDIM*SEQ)        // 8192
#define N1     (2*INTER+KEY)     // 3200

#define BM 128
#define BN 128
#define BK 64
#define STAGES 3
#define A_LDH 72                 // A rows: 64 halves + 8 pad (36 words % 32 = 4)
#define B_LD2 136                // B[k][n] rows: 128 halves + 8 pad
#define A_ST (128 * A_LDH)       // 9216 halves
#define B_ST (128 * A_LDH)
#define SMEM_BYTES (STAGES * (A_ST + B_ST) * 2)   // 110,592 B
#define NT  384                  // 8 consumer warps + 4 producer warps
#define NCW 8

// ---------------- scratch (device globals; no allocation allowed) ----------
__device__ __half g_u[(size_t)M_TOT * INTER];
__device__ __half g_v[(size_t)M_TOT * INTER];
__device__ __half g_q[(size_t)M_TOT * KEY];
__device__ __half g_k[(size_t)M_TOT * KEY];
__device__ __half g_attn[(size_t)BDIM * SEQ * SEQ];    // UNNORMALIZED exp(scores)
__device__ float  g_invZ[(size_t)M_TOT];
__device__ __half g_g[(size_t)M_TOT * INTER];
__device__ __half g_hs[(size_t)M_TOT * HIDDEN];
__device__ __half g_wi[(size_t)HIDDEN * N1];
__device__ __half g_wo[(size_t)INTER * HIDDEN];

// ---------------- helpers ---------------------------------------------------
__device__ __forceinline__ float silu(float x) { return x / (1.0f + expf(-x)); }

__device__ __forceinline__ void mma_f16(float (&c)[4], const uint32_t (&a)[4],
                                        const uint32_t (&b)[2]) {
    asm volatile(
        "mma.sync.aligned.m16n8k16.row.col.f32.f16.f16.f32 "
        "{%0,%1,%2,%3}, {%4,%5,%6,%7}, {%8,%9}, {%0,%1,%2,%3};"
        : "+f"(c[0]), "+f"(c[1]), "+f"(c[2]), "+f"(c[3])
        : "r"(a[0]), "r"(a[1]), "r"(a[2]), "r"(a[3]), "r"(b[0]), "r"(b[1]));
}

__device__ __forceinline__ void ldsm4(uint32_t& r0, uint32_t& r1,
                                      uint32_t& r2, uint32_t& r3, uint32_t addr) {
    asm volatile("ldmatrix.sync.aligned.m8n8.x4.shared.b16 {%0,%1,%2,%3}, [%4];"
                 : "=r"(r0), "=r"(r1), "=r"(r2), "=r"(r3) : "r"(addr));
}
__device__ __forceinline__ void ldsm4t(uint32_t& r0, uint32_t& r1,
                                       uint32_t& r2, uint32_t& r3, uint32_t addr) {
    asm volatile("ldmatrix.sync.aligned.m8n8.x4.trans.shared.b16 {%0,%1,%2,%3}, [%4];"
                 : "=r"(r0), "=r"(r1), "=r"(r2), "=r"(r3) : "r"(addr));
}

__device__ __forceinline__ void cp_async16(const __half* smem, const __half* gmem) {
    uint32_t s = (uint32_t)__cvta_generic_to_shared(smem);
    asm volatile("cp.async.cg.shared.global [%0], [%1], 16;" :: "r"(s), "l"(gmem));
}
#define CP_COMMIT() asm volatile("cp.async.commit_group;")
#define CP_WAIT1()  asm volatile("cp.async.wait_group 1;")

// ---------------- warp-specialized 3-stage BK=64 fp16 GEMM core --------------
// 384 threads: warps 0-7 consume (64x32 tiles), warps 8-11 produce (cp.async).
// A: [M][K] half K-major.
// BT=false: B [N][K] -> non-trans ldsm ; BT=true: B [K][N] -> trans ldsm
template <int KDIM, bool BT>
__device__ __forceinline__ void gemm_f16(const __half* __restrict__ A,
                                         const __half* __restrict__ B,
                                         int lda, int ldb,
                                         int m0, int n0,
                                         float (&acc)[4][4][4]) {
    extern __shared__ __align__(16) __half sh[];
    __half* Abuf = sh;
    __half* Bbuf = sh + STAGES * A_ST;

    const int tid  = threadIdx.x;
    const int lane = tid & 31;
    const int warp = tid >> 5;
    const bool prod = (warp >= NCW);
    const int ptid = tid - NCW * 32;      // 0..127 for producers
    const int wr   = warp >> 2;           // consumers: 0..1
    const int wc   = warp & 3;            // consumers: 0..3

    // consumer ldmatrix byte offsets
    const int lr = lane & 7;
    const int a_row = lr + ((lane >> 3) & 1) * 8;
    const int a_k   = (lane >> 4) * 8;
    uint32_t offA[4], offB[2];
    #pragma unroll
    for (int mi = 0; mi < 4; mi++)
        offA[mi] = ((wr * 64 + mi * 16 + a_row) * A_LDH + a_k) * 2;
    if (!BT) {
        const int t = lane >> 3;
        const int b_n = (t >> 1) * 8;
        const int b_k = (t & 1) * 8;
        #pragma unroll
        for (int p = 0; p < 2; p++)
            offB[p] = ((wc * 32 + p * 16 + b_n + lr) * A_LDH + b_k) * 2;
    } else {
        const int t = lane >> 3;
        const int b_k = (t & 1) * 8;
        const int b_n = (t >> 1) * 8;
        #pragma unroll
        for (int p = 0; p < 2; p++)
            offB[p] = ((b_k + lr) * B_LD2 + wc * 32 + p * 16 + b_n) * 2;
    }
    const uint32_t smbA = (uint32_t)__cvta_generic_to_shared(Abuf);
    const uint32_t smbB = (uint32_t)__cvta_generic_to_shared(Bbuf);

    constexpr int NIT = KDIM / BK;

    auto issue = [&](int it) {
        if (prod && it < NIT) {
            const int k0 = it * BK;
            __half* As = Abuf + (it % STAGES) * A_ST;
            __half* Bs = Bbuf + (it % STAGES) * B_ST;
            #pragma unroll
            for (int t = 0; t < 8; t++) {
                const int id = ptid + t * 128;      // 0..1023
                const int r  = id >> 3;             // 0..127
                const int c8 = (id & 7) * 8;
                cp_async16(As + r * A_LDH + c8,
                           A + (size_t)(m0 + r) * lda + k0 + c8);
            }
            if (!BT) {
                #pragma unroll
                for (int t = 0; t < 8; t++) {
                    const int id = ptid + t * 128;
                    const int r  = id >> 3;
                    const int c8 = (id & 7) * 8;
                    cp_async16(Bs + r * A_LDH + c8,
                               B + (size_t)(n0 + r) * ldb + k0 + c8);
                }
            } else {
                #pragma unroll
                for (int t = 0; t < 8; t++) {
                    const int id = ptid + t * 128;  // 0..1023
                    const int r  = id >> 4;         // 0..63
                    const int c8 = (id & 15) * 8;
                    cp_async16(Bs + r * B_LD2 + c8,
                               B + (size_t)(k0 + r) * ldb + n0 + c8);
                }
            }
        }
        CP_COMMIT();
    };

    issue(0);
    issue(1);

    for (int it = 0; it < NIT; ++it) {
        CP_WAIT1();          // producers: stage `it` complete; consumers: no-op
        __syncthreads();
        issue(it + 2);

        if (!prod) {
            const uint32_t As = smbA + (uint32_t)((it % STAGES) * A_ST * 2);
            const uint32_t Bs = smbB + (uint32_t)((it % STAGES) * B_ST * 2);

            uint32_t a[2][4][4], b[2][4][2];
            // load fragments for slice 0
            #pragma unroll
            for (int mi = 0; mi < 4; mi++)
                ldsm4(a[0][mi][0], a[0][mi][1], a[0][mi][2], a[0][mi][3],
                      As + offA[mi]);
            if (!BT) {
                ldsm4(b[0][0][0], b[0][0][1], b[0][1][0], b[0][1][1], Bs + offB[0]);
                ldsm4(b[0][2][0], b[0][2][1], b[0][3][0], b[0][3][1], Bs + offB[1]);
            } else {
                ldsm4t(b[0][0][0], b[0][0][1], b[0][1][0], b[0][1][1], Bs + offB[0]);
                ldsm4t(b[0][2][0], b[0][2][1], b[0][3][0], b[0][3][1], Bs + offB[1]);
            }

            #pragma unroll
            for (int s = 0; s < 4; s++) {       // 4 slices of k=16
                const int cur = s & 1, nxt = cur ^ 1;
                if (s < 3) {
                    const int kk = (s + 1) * 16;
                    #pragma unroll
                    for (int mi = 0; mi < 4; mi++)
                        ldsm4(a[nxt][mi][0], a[nxt][mi][1],
                              a[nxt][mi][2], a[nxt][mi][3],
                              As + offA[mi] + kk * 2);
                    if (!BT) {
                        ldsm4(b[nxt][0][0], b[nxt][0][1], b[nxt][1][0], b[nxt][1][1],
                              Bs + offB[0] + kk * 2);
                        ldsm4(b[nxt][2][0], b[nxt][2][1], b[nxt][3][0], b[nxt][3][1],
                              Bs + offB[1] + kk * 2);
                    } else {
                        ldsm4t(b[nxt][0][0], b[nxt][0][1], b[nxt][1][0], b[nxt][1][1],
                               Bs + offB[0] + kk * (B_LD2 * 2));
                        ldsm4t(b[nxt][2][0], b[nxt][2][1], b[nxt][3][0], b[nxt][3][1],
                               Bs + offB[1] + kk * (B_LD2 * 2));
                    }
                }
                #pragma unroll
                for (int mi = 0; mi < 4; mi++)
                    #pragma unroll
                    for (int nj = 0; nj < 4; nj++)
                        mma_f16(acc[mi][nj], a[cur][mi], b[cur][nj]);
            }
        }
    }
}

// Epilogue indices (consumer warps): m = m0 + wr*64 + mi*16 + gp + (e>=2 ? 8:0)
//                                    n = n0 + wc*32 + nj*8 + 2*tg + (e&1)

// ---------------- prepass: fp32 -> fp16 (same layout) ------------------------
__global__ __launch_bounds__(256) void k_round_h(const float4* __restrict__ src,
                                                 __half* __restrict__ dst, int n4) {
    const int i = blockIdx.x * 256 + threadIdx.x;
    if (i < n4) {
        const float4 v = src[i];
        __half2* d = (__half2*)(dst + i * 4);
        d[0] = __floats2half2_rn(v.x, v.y);
        d[1] = __floats2half2_rn(v.z, v.w);
    }
}

// ---------------- kernel 1: h = silu(X @ Wi + bi) -> u/v/q/k -----------------
__global__ __launch_bounds__(NT, 1) void k_gemm1(const float* __restrict__ bi,
                                                 const float* __restrict__ gamma,
                                                 const float* __restrict__ beta) {
    float acc[4][4][4] = {};
    const int m0 = blockIdx.y * BM;
    const int n0 = blockIdx.x * BN;
    gemm_f16<HIDDEN, true>(g_hs, g_wi, HIDDEN, N1, m0, n0, acc);

    const int lane = threadIdx.x & 31, warp = threadIdx.x >> 5;
    if (warp >= NCW) return;
    const int wr = warp >> 2, wc = warp & 3, gp = lane >> 2, tg = lane & 3;

    #pragma unroll
    for (int mi = 0; mi < 4; mi++)
        #pragma unroll
        for (int nj = 0; nj < 4; nj++)
            #pragma unroll
            for (int e = 0; e < 4; e++) {
                const int m = m0 + wr * 64 + mi * 16 + gp + ((e >> 1) << 3);
                const int n = n0 + wc * 32 + nj * 8 + 2 * tg + (e & 1);
                const float x = acc[mi][nj][e] + bi[n];
                const float sv = silu(x);
                if (n0 < INTER) {
                    g_u[(size_t)m * INTER + n] = __float2half_rn(sv);
                } else if (n0 < 2 * INTER) {
                    g_v[(size_t)m * INTER + (n - INTER)] = __float2half_rn(sv);
                } else {
                    const int c = n - 2 * INTER;
                    g_q[(size_t)m * KEY + c] =
                        __float2half_rn(sv * gamma[c] + beta[c]);
                    g_k[(size_t)m * KEY + c] =
                        __float2half_rn(sv * gamma[KEY + c] + beta[KEY + c]);
                }
            }
}

// ---------------- kernel 2: attn_unnorm = exp((q@k^T)*s1 + (1-mask)*s2) ------
__global__ __launch_bounds__(NT, 1) void k_scores(const int* __restrict__ mask) {
    const int b = blockIdx.z;
    const int tid = threadIdx.x, lane = tid & 31, warp = tid >> 5;

    __shared__ float s_red[8];
    if (tid < 256) {
        int cnt = 0;
        #pragma unroll
        for (int t = 0; t < 8; t++) cnt += mask[b * SEQ + tid + t * 256];
        #pragma unroll
        for (int o = 16; o > 0; o >>= 1) cnt += __shfl_xor_sync(0xFFFFFFFF, cnt, o);
        if (lane == 0) s_red[warp] = (float)cnt;
    }
    __syncthreads();
    float total = 0.0f;
    #pragma unroll
    for (int w = 0; w < 8; w++) total += s_red[w];
    const float l = fmaxf(total, 1.0f);
    const float scale = logf(l) * (1.0f / logf(512.0f));
    const float s1 = 0.08838834764831845f * scale;
    const float s2 = -1.0e12f * scale;
    __syncthreads();

    float acc[4][4][4] = {};
    const int m0 = blockIdx.y * BM;
    const int n0 = blockIdx.x * BN;
    gemm_f16<KEY, false>(g_q + (size_t)b * SEQ * KEY,
                         g_k + (size_t)b * SEQ * KEY,
                         KEY, KEY, m0, n0, acc);

    if (warp >= NCW) return;
    __half* at = g_attn + (size_t)b * SEQ * SEQ;
    const int wr = warp >> 2, wc = warp & 3, gp = lane >> 2, tg = lane & 3;

    #pragma unroll
    for (int nj = 0; nj < 4; nj++) {
        const int n = n0 + wc * 32 + nj * 8 + 2 * tg;
        const float am0 = (1.0f - (float)mask[b * SEQ + n    ]) * s2;
        const float am1 = (1.0f - (float)mask[b * SEQ + n + 1]) * s2;
        #pragma unroll
        for (int mi = 0; mi < 4; mi++) {
            const int m = m0 + wr * 64 + mi * 16 + gp;
            at[(size_t)m * SEQ + n    ]       = __float2half_rn(expf(acc[mi][nj][0] * s1 + am0));
            at[(size_t)m * SEQ + n + 1]       = __float2half_rn(expf(acc[mi][nj][1] * s1 + am1));
            at[(size_t)(m + 8) * SEQ + n    ] = __float2half_rn(expf(acc[mi][nj][2] * s1 + am0));
            at[(size_t)(m + 8) * SEQ + n + 1] = __float2half_rn(expf(acc[mi][nj][3] * s1 + am1));
        }
    }
}

// ---------------- kernel 3: invZ[row] = 1 / rowsum(attn_unnorm) --------------
__global__ __launch_bounds__(256) void k_sum() {
    const __half2* at = (const __half2*)(g_attn + (size_t)blockIdx.x * SEQ);
    const int tid = threadIdx.x;
    __shared__ float red[256];

    float s = 0.0f;
    #pragma unroll
    for (int t = 0; t < 4; t++) {
        const float2 f = __half22float2(at[tid + t * 256]);
        s += f.x + f.y;
    }
    red[tid] = s;
    __syncthreads();
    for (int st = 128; st > 0; st >>= 1) {
        if (tid < st) red[tid] += red[tid + st];
        __syncthreads();
    }
    if (tid == 0) g_invZ[blockIdx.x] = 1.0f / red[0];
}

// ---------------- kernel 4: g = half(u * (attn_unnorm @ v) * invZ) -----------
__global__ __launch_bounds__(NT, 1) void k_ctx() {
    const int b = blockIdx.z;
    float acc[4][4][4] = {};
    const int m0 = blockIdx.y * BM;
    const int n0 = blockIdx.x * BN;
    gemm_f16<SEQ, true>(g_attn + (size_t)b * SEQ * SEQ,
                        g_v + (size_t)b * SEQ * INTER,
                        SEQ, INTER, m0, n0, acc);

    const int lane = threadIdx.x & 31, warp = threadIdx.x >> 5;
    if (warp >= NCW) return;
    const int wr = warp >> 2, wc = warp & 3, gp = lane >> 2, tg = lane & 3;

    #pragma unroll
    for (int mi = 0; mi < 4; mi++)
        #pragma unroll
        for (int nj = 0; nj < 4; nj++)
            #pragma unroll
            for (int e = 0; e < 4; e++) {
                const int m = m0 + wr * 64 + mi * 16 + gp + ((e >> 1) << 3);
                const int n = n0 + wc * 32 + nj * 8 + 2 * tg + (e & 1);
                const size_t row = (size_t)b * SEQ + m;
                const size_t idx = row * INTER + n;
                const float ctx = acc[mi][nj][e] * g_invZ[row];
                g_g[idx] = __float2half_rn(__half2float(g_u[idx]) * ctx);
            }
}

// ---------------- kernel 5: out = g @ Wo + bo --------------------------------
__global__ __launch_bounds__(NT, 1) void k_out(const float* __restrict__ bo,
                                               float* __restrict__ out) {
    float acc[4][4][4] = {};
    const int m0 = blockIdx.y * BM;
    const int n0 = blockIdx.x * BN;
    gemm_f16<INTER, true>(g_g, g_wo, INTER, HIDDEN, m0, n0, acc);

    const int lane = threadIdx.x & 31, warp = threadIdx.x >> 5;
    if (warp >= NCW) return;
    const int wr = warp >> 2, wc = warp & 3, gp = lane >> 2, tg = lane & 3;

    #pragma unroll
    for (int mi = 0; mi < 4; mi++)
        #pragma unroll
        for (int nj = 0; nj < 4; nj++)
            #pragma unroll
            for (int e = 0; e < 4; e++) {
                const int m = m0 + wr * 64 + mi * 16 + gp + ((e >> 1) << 3);
                const int n = n0 + wc * 32 + nj * 8 + 2 * tg + (e & 1);
                out[(size_t)m * HIDDEN + n] = acc[mi][nj][e] + bo[n];
            }
}

// ---------------- launch ------------------------------------------------------
extern "C" void kernel_launch(void* const* d_in, const int* in_sizes, int n_in,
                              void* d_out, int out_size) {
    const float* hs    = (const float*)d_in[0];
    const int*   mask  = (const int*)  d_in[1];
    // d_in[2] = position_ids (unused)
    const float* Wi    = (const float*)d_in[3];
    const float* bi    = (const float*)d_in[4];
    const float* gamma = (const float*)d_in[5];
    const float* beta  = (const float*)d_in[6];
    const float* Wo    = (const float*)d_in[7];
    const float* bo    = (const float*)d_in[8];
    float* out = (float*)d_out;

    __half *p_hs, *p_wi, *p_wo;
    cudaGetSymbolAddress((void**)&p_hs, g_hs);
    cudaGetSymbolAddress((void**)&p_wi, g_wi);
    cudaGetSymbolAddress((void**)&p_wo, g_wo);

    cudaFuncSetAttribute(k_gemm1,  cudaFuncAttributeMaxDynamicSharedMemorySize, SMEM_BYTES);
    cudaFuncSetAttribute(k_scores, cudaFuncAttributeMaxDynamicSharedMemorySize, SMEM_BYTES);
    cudaFuncSetAttribute(k_ctx,    cudaFuncAttributeMaxDynamicSharedMemorySize, SMEM_BYTES);
    cudaFuncSetAttribute(k_out,    cudaFuncAttributeMaxDynamicSharedMemorySize, SMEM_BYTES);

    dim3 blk(256), gblk(NT);
    {   // hs -> half
        const int n4 = M_TOT * HIDDEN / 4;
        k_round_h<<<(n4 + 255) / 256, blk>>>((const float4*)hs, p_hs, n4);
    }
    {   // Wi -> half
        const int n4 = HIDDEN * N1 / 4;
        k_round_h<<<(n4 + 255) / 256, blk>>>((const float4*)Wi, p_wi, n4);
    }
    {   // Wo -> half
        const int n4 = INTER * HIDDEN / 4;
        k_round_h<<<(n4 + 255) / 256, blk>>>((const float4*)Wo, p_wo, n4);
    }

    k_gemm1<<<dim3(N1 / BN, M_TOT / BM), gblk, SMEM_BYTES>>>(bi, gamma, beta);
    k_scores<<<dim3(SEQ / BN, SEQ / BM, BDIM), gblk, SMEM_BYTES>>>(mask);
    k_sum<<<dim3(M_TOT), blk>>>();
    k_ctx<<<dim3(INTER / BN, SEQ / BM, BDIM), gblk, SMEM_BYTES>>>();
    k_out<<<dim3(HIDDEN / BN, M_TOT / BM), gblk, SMEM_BYTES>>>(bo, out);
}

// round 15
// speedup vs baseline: 1.0257x; 1.0257x over previous
#include <cuda_runtime.h>
#include <cuda_fp16.h>
#include <math.h>
#include <stdint.h>

#define HIDDEN 768
#define KEY    128
#define INTER  1536
#define BDIM   4
#define SEQ    2048
#define M_TOT  (BDIM*SEQ)        // 8192
#define N1     (2*INTER+KEY)     // 3200

#define BM 128
#define BN 64
#define BK 32
#define STAGES 4
#define T_LD  40                 // rows of 32 halves + 8 pad (20 words %32: quads distinct)
#define B_LD2 72                 // B[k][n] rows: 64 halves + 8 pad (36 words %32 = 4)
#define A_ST (128 * T_LD)        // 5120 halves
#define B_ST (64 * T_LD)         // 2560 halves (>= 32*72=2304 for trans variant)
#define SMEM_BYTES (STAGES * (A_ST + B_ST) * 2)   // 61,440 B -> 3 CTAs/SM

// ---------------- scratch (device globals; no allocation allowed) ----------
__device__ __half g_u[(size_t)M_TOT * INTER];
__device__ __half g_v[(size_t)M_TOT * INTER];
__device__ __half g_q[(size_t)M_TOT * KEY];
__device__ __half g_k[(size_t)M_TOT * KEY];
__device__ __half g_attn[(size_t)BDIM * SEQ * SEQ];    // UNNORMALIZED exp(scores)
__device__ float  g_invZ[(size_t)M_TOT];
__device__ __half g_g[(size_t)M_TOT * INTER];
__device__ __half g_hs[(size_t)M_TOT * HIDDEN];
__device__ __half g_wi[(size_t)HIDDEN * N1];
__device__ __half g_wo[(size_t)INTER * HIDDEN];

// ---------------- helpers ---------------------------------------------------
__device__ __forceinline__ float silu(float x) { return x / (1.0f + expf(-x)); }

__device__ __forceinline__ void mma_f16(float (&c)[4], const uint32_t (&a)[4],
                                        const uint32_t (&b)[2]) {
    asm volatile(
        "mma.sync.aligned.m16n8k16.row.col.f32.f16.f16.f32 "
        "{%0,%1,%2,%3}, {%4,%5,%6,%7}, {%8,%9}, {%0,%1,%2,%3};"
        : "+f"(c[0]), "+f"(c[1]), "+f"(c[2]), "+f"(c[3])
        : "r"(a[0]), "r"(a[1]), "r"(a[2]), "r"(a[3]), "r"(b[0]), "r"(b[1]));
}

__device__ __forceinline__ void ldsm4(uint32_t& r0, uint32_t& r1,
                                      uint32_t& r2, uint32_t& r3, uint32_t addr) {
    asm volatile("ldmatrix.sync.aligned.m8n8.x4.shared.b16 {%0,%1,%2,%3}, [%4];"
                 : "=r"(r0), "=r"(r1), "=r"(r2), "=r"(r3) : "r"(addr));
}
__device__ __forceinline__ void ldsm4t(uint32_t& r0, uint32_t& r1,
                                       uint32_t& r2, uint32_t& r3, uint32_t addr) {
    asm volatile("ldmatrix.sync.aligned.m8n8.x4.trans.shared.b16 {%0,%1,%2,%3}, [%4];"
                 : "=r"(r0), "=r"(r1), "=r"(r2), "=r"(r3) : "r"(addr));
}

__device__ __forceinline__ void cp_async16(const __half* smem, const __half* gmem) {
    uint32_t s = (uint32_t)__cvta_generic_to_shared(smem);
    asm volatile("cp.async.cg.shared.global [%0], [%1], 16;" :: "r"(s), "l"(gmem));
}
#define CP_COMMIT() asm volatile("cp.async.commit_group;")
#define CP_WAIT2()  asm volatile("cp.async.wait_group 2;")

// ---------------- 4-stage BK=32 fp16 GEMM core, 128x64 block -----------------
// 256 threads = 8 warps (4x2); warp tile 32x32.
// A: [M][K] half K-major.
// BT=false: B [N][K] -> non-trans ldsm ; BT=true: B [K][N] -> trans ldsm
template <int KDIM, bool BT>
__device__ __forceinline__ void gemm_f16(const __half* __restrict__ A,
                                         const __half* __restrict__ B,
                                         int lda, int ldb,
                                         int m0, int n0,
                                         float (&acc)[2][4][4]) {
    extern __shared__ __align__(16) __half sh[];
    __half* Abuf = sh;                    // STAGES * A_ST
    __half* Bbuf = sh + STAGES * A_ST;    // STAGES * B_ST

    const int tid  = threadIdx.x;
    const int lane = tid & 31;
    const int warp = tid >> 5;
    const int wr   = warp >> 1;   // 0..3 -> m offset 32
    const int wc   = warp & 1;    // 0..1 -> n offset 32

    const int lr = lane & 7;
    const int a_row = lr + ((lane >> 3) & 1) * 8;
    const int a_k   = (lane >> 4) * 8;
    uint32_t offA[2], offB[2];
    #pragma unroll
    for (int mi = 0; mi < 2; mi++)
        offA[mi] = ((wr * 32 + mi * 16 + a_row) * T_LD + a_k) * 2;
    if (!BT) {
        const int t = lane >> 3;
        const int b_n = (t >> 1) * 8;
        const int b_k = (t & 1) * 8;
        #pragma unroll
        for (int p = 0; p < 2; p++)
            offB[p] = ((wc * 32 + p * 16 + b_n + lr) * T_LD + b_k) * 2;
    } else {
        const int t = lane >> 3;
        const int b_k = (t & 1) * 8;
        const int b_n = (t >> 1) * 8;
        #pragma unroll
        for (int p = 0; p < 2; p++)
            offB[p] = ((b_k + lr) * B_LD2 + wc * 32 + p * 16 + b_n) * 2;
    }
    const uint32_t smbA = (uint32_t)__cvta_generic_to_shared(Abuf);
    const uint32_t smbB = (uint32_t)__cvta_generic_to_shared(Bbuf);

    constexpr int NIT = KDIM / BK;

    auto issue = [&](int it) {
        if (it < NIT) {
            const int k0 = it * BK;
            __half* As = Abuf + (it % STAGES) * A_ST;
            __half* Bs = Bbuf + (it % STAGES) * B_ST;
            // A: 128 rows x 32 halves = 512 chunks
            #pragma unroll
            for (int t = 0; t < 2; t++) {
                const int id = tid + t * 256;
                const int r  = id >> 2;             // 0..127
                const int c8 = (id & 3) * 8;
                cp_async16(As + r * T_LD + c8,
                           A + (size_t)(m0 + r) * lda + k0 + c8);
            }
            if (!BT) {
                // B [n][k]: 64 rows x 32 halves = 256 chunks
                if (tid < 256) {
                    const int r  = tid >> 2;        // 0..63
                    const int c8 = (tid & 3) * 8;
                    cp_async16(Bs + r * T_LD + c8,
                               B + (size_t)(n0 + r) * ldb + k0 + c8);
                }
            } else {
                // B [k][n]: 32 rows x 64 halves = 256 chunks
                if (tid < 256) {
                    const int r  = tid >> 3;        // 0..31
                    const int c8 = (tid & 7) * 8;
                    cp_async16(Bs + r * B_LD2 + c8,
                               B + (size_t)(k0 + r) * ldb + n0 + c8);
                }
            }
        }
        CP_COMMIT();
    };

    issue(0);
    issue(1);
    issue(2);

    for (int it = 0; it < NIT; ++it) {
        CP_WAIT2();
        __syncthreads();
        issue(it + 3);

        const uint32_t As = smbA + (uint32_t)((it % STAGES) * A_ST * 2);
        const uint32_t Bs = smbB + (uint32_t)((it % STAGES) * B_ST * 2);

        #pragma unroll
        for (int kk = 0; kk < BK; kk += 16) {
            uint32_t a[2][4], b[4][2];
            #pragma unroll
            for (int mi = 0; mi < 2; mi++)
                ldsm4(a[mi][0], a[mi][1], a[mi][2], a[mi][3],
                      As + offA[mi] + kk * 2);
            if (!BT) {
                ldsm4(b[0][0], b[0][1], b[1][0], b[1][1], Bs + offB[0] + kk * 2);
                ldsm4(b[2][0], b[2][1], b[3][0], b[3][1], Bs + offB[1] + kk * 2);
            } else {
                ldsm4t(b[0][0], b[0][1], b[1][0], b[1][1],
                       Bs + offB[0] + kk * (B_LD2 * 2));
                ldsm4t(b[2][0], b[2][1], b[3][0], b[3][1],
                       Bs + offB[1] + kk * (B_LD2 * 2));
            }
            #pragma unroll
            for (int mi = 0; mi < 2; mi++)
                #pragma unroll
                for (int nj = 0; nj < 4; nj++)
                    mma_f16(acc[mi][nj], a[mi], b[nj]);
        }
    }
}

// Epilogue indices: m = m0 + wr*32 + mi*16 + gp + (e>=2 ? 8 : 0)
//                   n = n0 + wc*32 + nj*8 + 2*tg + (e&1)

// ---------------- prepass: fp32 -> fp16 (same layout) ------------------------
__global__ __launch_bounds__(256) void k_round_h(const float4* __restrict__ src,
                                                 __half* __restrict__ dst, int n4) {
    const int i = blockIdx.x * 256 + threadIdx.x;
    if (i < n4) {
        const float4 v = src[i];
        __half2* d = (__half2*)(dst + i * 4);
        d[0] = __floats2half2_rn(v.x, v.y);
        d[1] = __floats2half2_rn(v.z, v.w);
    }
}

// ---------------- kernel 1: h = silu(X @ Wi + bi) -> u/v/q/k -----------------
__global__ __launch_bounds__(256, 3) void k_gemm1(const float* __restrict__ bi,
                                                  const float* __restrict__ gamma,
                                                  const float* __restrict__ beta) {
    float acc[2][4][4] = {};
    const int m0 = blockIdx.y * BM;
    const int n0 = blockIdx.x * BN;
    gemm_f16<HIDDEN, true>(g_hs, g_wi, HIDDEN, N1, m0, n0, acc);

    const int lane = threadIdx.x & 31, warp = threadIdx.x >> 5;
    const int wr = warp >> 1, wc = warp & 1, gp = lane >> 2, tg = lane & 3;

    #pragma unroll
    for (int mi = 0; mi < 2; mi++)
        #pragma unroll
        for (int nj = 0; nj < 4; nj++)
            #pragma unroll
            for (int e = 0; e < 4; e++) {
                const int m = m0 + wr * 32 + mi * 16 + gp + ((e >> 1) << 3);
                const int n = n0 + wc * 32 + nj * 8 + 2 * tg + (e & 1);
                const float x = acc[mi][nj][e] + bi[n];
                const float sv = silu(x);
                if (n0 < INTER) {
                    g_u[(size_t)m * INTER + n] = __float2half_rn(sv);
                } else if (n0 < 2 * INTER) {
                    g_v[(size_t)m * INTER + (n - INTER)] = __float2half_rn(sv);
                } else {
                    const int c = n - 2 * INTER;
                    g_q[(size_t)m * KEY + c] =
                        __float2half_rn(sv * gamma[c] + beta[c]);
                    g_k[(size_t)m * KEY + c] =
                        __float2half_rn(sv * gamma[KEY + c] + beta[KEY + c]);
                }
            }
}

// ---------------- kernel 2: attn_unnorm = exp((q@k^T)*s1 + (1-mask)*s2) ------
__global__ __launch_bounds__(256, 3) void k_scores(const int* __restrict__ mask) {
    const int b = blockIdx.z;
    const int tid = threadIdx.x, lane = tid & 31, warp = tid >> 5;

    __shared__ float s_red[8];
    int cnt = 0;
    #pragma unroll
    for (int t = 0; t < 8; t++) cnt += mask[b * SEQ + tid + t * 256];
    #pragma unroll
    for (int o = 16; o > 0; o >>= 1) cnt += __shfl_xor_sync(0xFFFFFFFF, cnt, o);
    if (lane == 0) s_red[warp] = (float)cnt;
    __syncthreads();
    float total = 0.0f;
    #pragma unroll
    for (int w = 0; w < 8; w++) total += s_red[w];
    const float l = fmaxf(total, 1.0f);
    const float scale = logf(l) * (1.0f / logf(512.0f));
    const float s1 = 0.08838834764831845f * scale;
    const float s2 = -1.0e12f * scale;
    __syncthreads();

    float acc[2][4][4] = {};
    const int m0 = blockIdx.y * BM;
    const int n0 = blockIdx.x * BN;
    gemm_f16<KEY, false>(g_q + (size_t)b * SEQ * KEY,
                         g_k + (size_t)b * SEQ * KEY,
                         KEY, KEY, m0, n0, acc);

    __half* at = g_attn + (size_t)b * SEQ * SEQ;
    const int wr = warp >> 1, wc = warp & 1, gp = lane >> 2, tg = lane & 3;

    #pragma unroll
    for (int nj = 0; nj < 4; nj++) {
        const int n = n0 + wc * 32 + nj * 8 + 2 * tg;
        const float am0 = (1.0f - (float)mask[b * SEQ + n    ]) * s2;
        const float am1 = (1.0f - (float)mask[b * SEQ + n + 1]) * s2;
        #pragma unroll
        for (int mi = 0; mi < 2; mi++) {
            const int m = m0 + wr * 32 + mi * 16 + gp;
            at[(size_t)m * SEQ + n    ]       = __float2half_rn(expf(acc[mi][nj][0] * s1 + am0));
            at[(size_t)m * SEQ + n + 1]       = __float2half_rn(expf(acc[mi][nj][1] * s1 + am1));
            at[(size_t)(m + 8) * SEQ + n    ] = __float2half_rn(expf(acc[mi][nj][2] * s1 + am0));
            at[(size_t)(m + 8) * SEQ + n + 1] = __float2half_rn(expf(acc[mi][nj][3] * s1 + am1));
        }
    }
}

// ---------------- kernel 3: invZ[row] = 1 / rowsum(attn_unnorm) --------------
__global__ __launch_bounds__(256) void k_sum() {
    const __half2* at = (const __half2*)(g_attn + (size_t)blockIdx.x * SEQ);
    const int tid = threadIdx.x;
    __shared__ float red[256];

    float s = 0.0f;
    #pragma unroll
    for (int t = 0; t < 4; t++) {
        const float2 f = __half22float2(at[tid + t * 256]);
        s += f.x + f.y;
    }
    red[tid] = s;
    __syncthreads();
    for (int st = 128; st > 0; st >>= 1) {
        if (tid < st) red[tid] += red[tid + st];
        __syncthreads();
    }
    if (tid == 0) g_invZ[blockIdx.x] = 1.0f / red[0];
}

// ---------------- kernel 4: g = half(u * (attn_unnorm @ v) * invZ) -----------
__global__ __launch_bounds__(256, 3) void k_ctx() {
    const int b = blockIdx.z;
    float acc[2][4][4] = {};
    const int m0 = blockIdx.y * BM;
    const int n0 = blockIdx.x * BN;
    gemm_f16<SEQ, true>(g_attn + (size_t)b * SEQ * SEQ,
                        g_v + (size_t)b * SEQ * INTER,
                        SEQ, INTER, m0, n0, acc);

    const int lane = threadIdx.x & 31, warp = threadIdx.x >> 5;
    const int wr = warp >> 1, wc = warp & 1, gp = lane >> 2, tg = lane & 3;

    #pragma unroll
    for (int mi = 0; mi < 2; mi++)
        #pragma unroll
        for (int nj = 0; nj < 4; nj++)
            #pragma unroll
            for (int e = 0; e < 4; e++) {
                const int m = m0 + wr * 32 + mi * 16 + gp + ((e >> 1) << 3);
                const int n = n0 + wc * 32 + nj * 8 + 2 * tg + (e & 1);
                const size_t row = (size_t)b * SEQ + m;
                const size_t idx = row * INTER + n;
                const float ctx = acc[mi][nj][e] * g_invZ[row];
                g_g[idx] = __float2half_rn(__half2float(g_u[idx]) * ctx);
            }
}

// ---------------- kernel 5: out = g @ Wo + bo --------------------------------
__global__ __launch_bounds__(256, 3) void k_out(const float* __restrict__ bo,
                                                float* __restrict__ out) {
    float acc[2][4][4] = {};
    const int m0 = blockIdx.y * BM;
    const int n0 = blockIdx.x * BN;
    gemm_f16<INTER, true>(g_g, g_wo, INTER, HIDDEN, m0, n0, acc);

    const int lane = threadIdx.x & 31, warp = threadIdx.x >> 5;
    const int wr = warp >> 1, wc = warp & 1, gp = lane >> 2, tg = lane & 3;

    #pragma unroll
    for (int mi = 0; mi < 2; mi++)
        #pragma unroll
        for (int nj = 0; nj < 4; nj++)
            #pragma unroll
            for (int e = 0; e < 4; e++) {
                const int m = m0 + wr * 32 + mi * 16 + gp + ((e >> 1) << 3);
                const int n = n0 + wc * 32 + nj * 8 + 2 * tg + (e & 1);
                out[(size_t)m * HIDDEN + n] = acc[mi][nj][e] + bo[n];
            }
}

// ---------------- launch ------------------------------------------------------
extern "C" void kernel_launch(void* const* d_in, const int* in_sizes, int n_in,
                              void* d_out, int out_size) {
    const float* hs    = (const float*)d_in[0];
    const int*   mask  = (const int*)  d_in[1];
    // d_in[2] = position_ids (unused)
    const float* Wi    = (const float*)d_in[3];
    const float* bi    = (const float*)d_in[4];
    const float* gamma = (const float*)d_in[5];
    const float* beta  = (const float*)d_in[6];
    const float* Wo    = (const float*)d_in[7];
    const float* bo    = (const float*)d_in[8];
    float* out = (float*)d_out;

    __half *p_hs, *p_wi, *p_wo;
    cudaGetSymbolAddress((void**)&p_hs, g_hs);
    cudaGetSymbolAddress((void**)&p_wi, g_wi);
    cudaGetSymbolAddress((void**)&p_wo, g_wo);

    cudaFuncSetAttribute(k_gemm1,  cudaFuncAttributeMaxDynamicSharedMemorySize, SMEM_BYTES);
    cudaFuncSetAttribute(k_scores, cudaFuncAttributeMaxDynamicSharedMemorySize, SMEM_BYTES);
    cudaFuncSetAttribute(k_ctx,    cudaFuncAttributeMaxDynamicSharedMemorySize, SMEM_BYTES);
    cudaFuncSetAttribute(k_out,    cudaFuncAttributeMaxDynamicSharedMemorySize, SMEM_BYTES);

    dim3 blk(256);
    {   // hs -> half
        const int n4 = M_TOT * HIDDEN / 4;
        k_round_h<<<(n4 + 255) / 256, blk>>>((const float4*)hs, p_hs, n4);
    }
    {   // Wi -> half
        const int n4 = HIDDEN * N1 / 4;
        k_round_h<<<(n4 + 255) / 256, blk>>>((const float4*)Wi, p_wi, n4);
    }
    {   // Wo -> half
        const int n4 = INTER * HIDDEN / 4;
        k_round_h<<<(n4 + 255) / 256, blk>>>((const float4*)Wo, p_wo, n4);
    }

    k_gemm1<<<dim3(N1 / BN, M_TOT / BM), blk, SMEM_BYTES>>>(bi, gamma, beta);
    k_scores<<<dim3(SEQ / BN, SEQ / BM, BDIM), blk, SMEM_BYTES>>>(mask);
    k_sum<<<dim3(M_TOT), blk>>>();
    k_ctx<<<dim3(INTER / BN, SEQ / BM, BDIM), blk, SMEM_BYTES>>>();
    k_out<<<dim3(HIDDEN / BN, M_TOT / BM), blk, SMEM_BYTES>>>(bo, out);
}

// round 16
// speedup vs baseline: 1.3359x; 1.3025x over previous
#include <cuda_runtime.h>
#include <cuda_fp16.h>
#include <math.h>
#include <stdint.h>

#define HIDDEN 768
#define KEY    128
#define INTER  1536
#define BDIM   4
#define SEQ    2048
#define M_TOT  (BDIM*SEQ)        // 8192
#define N1     (2*INTER+KEY)     // 3200

#define BM 128
#define BN 128
#define BK 64
#define STAGES 3
#define A_LDH 72                 // rows: 64 halves + 8 pad (36 words % 32 = 4)
#define B_LD2 136                // B[k][n] rows: 128 halves + 8 pad
#define A_ST (128 * A_LDH)
#define B_ST (128 * A_LDH)
#define SMEM_BYTES (STAGES * (A_ST + B_ST) * 2)   // 110,592 B -> 2 CTAs/SM

// ---------------- scratch (device globals; no allocation allowed) ----------
__device__ __half g_u[(size_t)M_TOT * INTER];
__device__ __half g_v[(size_t)M_TOT * INTER];
__device__ __half g_q[(size_t)M_TOT * KEY];
__device__ __half g_k[(size_t)M_TOT * KEY];
__device__ __half g_kp[(size_t)M_TOT * KEY];           // compacted k (pad rows stay 0)
__device__ __half g_vp[(size_t)M_TOT * INTER];         // compacted v (pad rows stay 0)
__device__ int    g_idx[(size_t)M_TOT];                // valid-key indices per batch
__device__ int    g_L[BDIM];                           // valid-key counts
__device__ __half g_attn[(size_t)BDIM * SEQ * SEQ];    // unnorm exp(scores), compact cols
__device__ float  g_invZ[(size_t)M_TOT];
__device__ __half g_g[(size_t)M_TOT * INTER];
__device__ __half g_hs[(size_t)M_TOT * HIDDEN];
__device__ __half g_wi[(size_t)HIDDEN * N1];
__device__ __half g_wo[(size_t)INTER * HIDDEN];

// ---------------- helpers ---------------------------------------------------
__device__ __forceinline__ float silu(float x) { return x / (1.0f + expf(-x)); }

__device__ __forceinline__ void mma_f16(float (&c)[4], const uint32_t (&a)[4],
                                        const uint32_t (&b)[2]) {
    asm volatile(
        "mma.sync.aligned.m16n8k16.row.col.f32.f16.f16.f32 "
        "{%0,%1,%2,%3}, {%4,%5,%6,%7}, {%8,%9}, {%0,%1,%2,%3};"
        : "+f"(c[0]), "+f"(c[1]), "+f"(c[2]), "+f"(c[3])
        : "r"(a[0]), "r"(a[1]), "r"(a[2]), "r"(a[3]), "r"(b[0]), "r"(b[1]));
}

__device__ __forceinline__ void ldsm4(uint32_t& r0, uint32_t& r1,
                                      uint32_t& r2, uint32_t& r3, uint32_t addr) {
    asm volatile("ldmatrix.sync.aligned.m8n8.x4.shared.b16 {%0,%1,%2,%3}, [%4];"
                 : "=r"(r0), "=r"(r1), "=r"(r2), "=r"(r3) : "r"(addr));
}
__device__ __forceinline__ void ldsm4t(uint32_t& r0, uint32_t& r1,
                                       uint32_t& r2, uint32_t& r3, uint32_t addr) {
    asm volatile("ldmatrix.sync.aligned.m8n8.x4.trans.shared.b16 {%0,%1,%2,%3}, [%4];"
                 : "=r"(r0), "=r"(r1), "=r"(r2), "=r"(r3) : "r"(addr));
}

__device__ __forceinline__ void cp_async16(const __half* smem, const __half* gmem) {
    uint32_t s = (uint32_t)__cvta_generic_to_shared(smem);
    asm volatile("cp.async.cg.shared.global [%0], [%1], 16;" :: "r"(s), "l"(gmem));
}
#define CP_COMMIT() asm volatile("cp.async.commit_group;")
#define CP_WAIT1()  asm volatile("cp.async.wait_group 1;")

// ---------------- 3-stage BK=64 fp16 GEMM core (runtime K) -------------------
// 256 threads = 8 warps (2x4); warp tile 64x32; block tile 128x128.
// A: [M][K] half K-major.
// BT=false: B [N][K] -> non-trans ldsm ; BT=true: B [K][N] -> trans ldsm
template <bool BT>
__device__ __forceinline__ void gemm_f16(const __half* __restrict__ A,
                                         const __half* __restrict__ B,
                                         int lda, int ldb,
                                         int m0, int n0, int kdim,
                                         float (&acc)[4][4][4]) {
    extern __shared__ __align__(16) __half sh[];
    __half* Abuf = sh;
    __half* Bbuf = sh + STAGES * A_ST;

    const int tid  = threadIdx.x;
    const int lane = tid & 31;
    const int warp = tid >> 5;
    const int wr   = warp >> 2;
    const int wc   = warp & 3;

    const int lr = lane & 7;
    const int a_row = lr + ((lane >> 3) & 1) * 8;
    const int a_k   = (lane >> 4) * 8;
    uint32_t offA[4], offB[2];
    #pragma unroll
    for (int mi = 0; mi < 4; mi++)
        offA[mi] = ((wr * 64 + mi * 16 + a_row) * A_LDH + a_k) * 2;
    if (!BT) {
        const int t = lane >> 3;
        const int b_n = (t >> 1) * 8;
        const int b_k = (t & 1) * 8;
        #pragma unroll
        for (int p = 0; p < 2; p++)
            offB[p] = ((wc * 32 + p * 16 + b_n + lr) * A_LDH + b_k) * 2;
    } else {
        const int t = lane >> 3;
        const int b_k = (t & 1) * 8;
        const int b_n = (t >> 1) * 8;
        #pragma unroll
        for (int p = 0; p < 2; p++)
            offB[p] = ((b_k + lr) * B_LD2 + wc * 32 + p * 16 + b_n) * 2;
    }
    const uint32_t smbA = (uint32_t)__cvta_generic_to_shared(Abuf);
    const uint32_t smbB = (uint32_t)__cvta_generic_to_shared(Bbuf);

    const int nit = kdim / BK;

    auto issue = [&](int it) {
        if (it < nit) {
            const int k0 = it * BK;
            __half* As = Abuf + (it % STAGES) * A_ST;
            __half* Bs = Bbuf + (it % STAGES) * B_ST;
            #pragma unroll
            for (int t = 0; t < 4; t++) {
                const int id = tid + t * 256;
                const int r  = id >> 3;
                const int c8 = (id & 7) * 8;
                cp_async16(As + r * A_LDH + c8,
                           A + (size_t)(m0 + r) * lda + k0 + c8);
            }
            if (!BT) {
                #pragma unroll
                for (int t = 0; t < 4; t++) {
                    const int id = tid + t * 256;
                    const int r  = id >> 3;
                    const int c8 = (id & 7) * 8;
                    cp_async16(Bs + r * A_LDH + c8,
                               B + (size_t)(n0 + r) * ldb + k0 + c8);
                }
            } else {
                #pragma unroll
                for (int t = 0; t < 4; t++) {
                    const int id = tid + t * 256;
                    const int r  = id >> 4;
                    const int c8 = (id & 15) * 8;
                    cp_async16(Bs + r * B_LD2 + c8,
                               B + (size_t)(k0 + r) * ldb + n0 + c8);
                }
            }
        }
        CP_COMMIT();
    };

    issue(0);
    issue(1);

    for (int it = 0; it < nit; ++it) {
        CP_WAIT1();
        __syncthreads();
        issue(it + 2);

        const uint32_t As = smbA + (uint32_t)((it % STAGES) * A_ST * 2);
        const uint32_t Bs = smbB + (uint32_t)((it % STAGES) * B_ST * 2);

        #pragma unroll
        for (int kk = 0; kk < BK; kk += 16) {
            uint32_t a[4][4], b[4][2];
            #pragma unroll
            for (int mi = 0; mi < 4; mi++)
                ldsm4(a[mi][0], a[mi][1], a[mi][2], a[mi][3],
                      As + offA[mi] + kk * 2);
            if (!BT) {
                ldsm4(b[0][0], b[0][1], b[1][0], b[1][1], Bs + offB[0] + kk * 2);
                ldsm4(b[2][0], b[2][1], b[3][0], b[3][1], Bs + offB[1] + kk * 2);
            } else {
                ldsm4t(b[0][0], b[0][1], b[1][0], b[1][1],
                       Bs + offB[0] + kk * (B_LD2 * 2));
                ldsm4t(b[2][0], b[2][1], b[3][0], b[3][1],
                       Bs + offB[1] + kk * (B_LD2 * 2));
            }
            #pragma unroll
            for (int mi = 0; mi < 4; mi++)
                #pragma unroll
                for (int nj = 0; nj < 4; nj++)
                    mma_f16(acc[mi][nj], a[mi], b[nj]);
        }
    }
}

// Epilogue indices: m = m0 + wr*64 + mi*16 + gp + (e>=2 ? 8 : 0)
//                   n = n0 + wc*32 + nj*8 + 2*tg + (e&1)

// ---------------- prepass: fp32 -> fp16 --------------------------------------
__global__ __launch_bounds__(256) void k_round_h(const float4* __restrict__ src,
                                                 __half* __restrict__ dst, int n4) {
    const int i = blockIdx.x * 256 + threadIdx.x;
    if (i < n4) {
        const float4 v = src[i];
        __half2* d = (__half2*)(dst + i * 4);
        d[0] = __floats2half2_rn(v.x, v.y);
        d[1] = __floats2half2_rn(v.z, v.w);
    }
}

// ---------------- mask compaction: idx list + count per batch ----------------
__global__ __launch_bounds__(256) void k_compact(const int* __restrict__ mask) {
    const int b = blockIdx.x;
    const int tid = threadIdx.x;
    __shared__ int red[256];
    int v[8], t = 0;
    #pragma unroll
    for (int i = 0; i < 8; i++) {
        v[i] = mask[b * SEQ + tid * 8 + i];
        t += v[i];
    }
    red[tid] = t;
    __syncthreads();
    for (int o = 1; o < 256; o <<= 1) {
        int x = (tid >= o) ? red[tid - o] : 0;
        __syncthreads();
        red[tid] += x;
        __syncthreads();
    }
    int pos = red[tid] - t;                 // exclusive prefix
    #pragma unroll
    for (int i = 0; i < 8; i++)
        if (v[i]) g_idx[b * SEQ + pos++] = tid * 8 + i;
    if (tid == 255) g_L[b] = red[255];
}

// ---------------- gather valid k/v rows into dense prefix --------------------
__global__ __launch_bounds__(256) void k_gather() {
    const int b = blockIdx.y;
    const int i = blockIdx.x;
    if (i >= g_L[b]) return;                // pad rows stay zero (zero-init, never written)
    const int tid = threadIdx.x;
    const int src = g_idx[b * SEQ + i];
    const uint4* ks = (const uint4*)(g_k + ((size_t)b * SEQ + src) * KEY);
    uint4*       kd = (uint4*)(g_kp + ((size_t)b * SEQ + i) * KEY);
    if (tid < 16) kd[tid] = ks[tid];        // 128 halves
    const uint4* vs = (const uint4*)(g_v + ((size_t)b * SEQ + src) * INTER);
    uint4*       vd = (uint4*)(g_vp + ((size_t)b * SEQ + i) * INTER);
    if (tid < 192) vd[tid] = vs[tid];       // 1536 halves
}

// ---------------- kernel 1: h = silu(X @ Wi + bi) -> u/v/q/k -----------------
__global__ __launch_bounds__(256, 2) void k_gemm1(const float* __restrict__ bi,
                                                  const float* __restrict__ gamma,
                                                  const float* __restrict__ beta) {
    float acc[4][4][4] = {};
    const int m0 = blockIdx.y * BM;
    const int n0 = blockIdx.x * BN;
    gemm_f16<true>(g_hs, g_wi, HIDDEN, N1, m0, n0, HIDDEN, acc);

    const int lane = threadIdx.x & 31, warp = threadIdx.x >> 5;
    const int wr = warp >> 2, wc = warp & 3, gp = lane >> 2, tg = lane & 3;

    #pragma unroll
    for (int mi = 0; mi < 4; mi++)
        #pragma unroll
        for (int nj = 0; nj < 4; nj++)
            #pragma unroll
            for (int e = 0; e < 4; e++) {
                const int m = m0 + wr * 64 + mi * 16 + gp + ((e >> 1) << 3);
                const int n = n0 + wc * 32 + nj * 8 + 2 * tg + (e & 1);
                const float x = acc[mi][nj][e] + bi[n];
                const float sv = silu(x);
                if (n0 < INTER) {
                    g_u[(size_t)m * INTER + n] = __float2half_rn(sv);
                } else if (n0 < 2 * INTER) {
                    g_v[(size_t)m * INTER + (n - INTER)] = __float2half_rn(sv);
                } else {
                    const int c = n - 2 * INTER;
                    g_q[(size_t)m * KEY + c] =
                        __float2half_rn(sv * gamma[c] + beta[c]);
                    g_k[(size_t)m * KEY + c] =
                        __float2half_rn(sv * gamma[KEY + c] + beta[KEY + c]);
                }
            }
}

// ---------------- kernel 2: attn = exp((q@kp^T)*s1) over compact keys --------
// Masked keys are gone (their softmax weight is exactly 0 = exp(-1e12*scale)
// underflow in the reference). Pad columns [L, Lceil128) get explicit 0.
__global__ __launch_bounds__(256, 2) void k_scores() {
    const int b = blockIdx.z;
    const int L = g_L[b];
    const int Lc = (L + 127) & ~127;        // Lceil128
    const int n0 = blockIdx.x * BN;
    if (n0 >= Lc) return;                   // block-uniform early exit

    const float l = fmaxf((float)L, 1.0f);
    const float scale = logf(l) * (1.0f / logf(512.0f));
    const float s1 = 0.08838834764831845f * scale;

    float acc[4][4][4] = {};
    const int m0 = blockIdx.y * BM;
    gemm_f16<false>(g_q + (size_t)b * SEQ * KEY,
                    g_kp + (size_t)b * SEQ * KEY,
                    KEY, KEY, m0, n0, KEY, acc);

    __half* at = g_attn + (size_t)b * SEQ * SEQ;
    const int lane = threadIdx.x & 31, warp = threadIdx.x >> 5;
    const int wr = warp >> 2, wc = warp & 3, gp = lane >> 2, tg = lane & 3;

    #pragma unroll
    for (int nj = 0; nj < 4; nj++) {
        const int n = n0 + wc * 32 + nj * 8 + 2 * tg;
        const bool v0 = (n     < L);
        const bool v1 = (n + 1 < L);
        #pragma unroll
        for (int mi = 0; mi < 4; mi++) {
            const int m = m0 + wr * 64 + mi * 16 + gp;
            at[(size_t)m * SEQ + n    ]       = v0 ? __float2half_rn(expf(acc[mi][nj][0] * s1)) : __half(0.0f);
            at[(size_t)m * SEQ + n + 1]       = v1 ? __float2half_rn(expf(acc[mi][nj][1] * s1)) : __half(0.0f);
            at[(size_t)(m + 8) * SEQ + n    ] = v0 ? __float2half_rn(expf(acc[mi][nj][2] * s1)) : __half(0.0f);
            at[(size_t)(m + 8) * SEQ + n + 1] = v1 ? __float2half_rn(expf(acc[mi][nj][3] * s1)) : __half(0.0f);
        }
    }
}

// ---------------- kernel 3: invZ[row] = 1 / rowsum -------------------------
// Columns >= Lceil128 are never written and stay zero (zero-init) -> full-row
// sum is correct and deterministic.
__global__ __launch_bounds__(256) void k_sum() {
    const __half2* at = (const __half2*)(g_attn + (size_t)blockIdx.x * SEQ);
    const int tid = threadIdx.x;
    __shared__ float red[256];

    float s = 0.0f;
    #pragma unroll
    for (int t = 0; t < 4; t++) {
        const float2 f = __half22float2(at[tid + t * 256]);
        s += f.x + f.y;
    }
    red[tid] = s;
    __syncthreads();
    for (int st = 128; st > 0; st >>= 1) {
        if (tid < st) red[tid] += red[tid + st];
        __syncthreads();
    }
    if (tid == 0) g_invZ[blockIdx.x] = 1.0f / red[0];
}

// ---------------- kernel 4: g = half(u * (attn @ vp) * invZ), K = Lceil128 ---
__global__ __launch_bounds__(256, 2) void k_ctx() {
    const int b = blockIdx.z;
    const int Lc = (g_L[b] + 127) & ~127;
    float acc[4][4][4] = {};
    const int m0 = blockIdx.y * BM;
    const int n0 = blockIdx.x * BN;
    gemm_f16<true>(g_attn + (size_t)b * SEQ * SEQ,
                   g_vp + (size_t)b * SEQ * INTER,
                   SEQ, INTER, m0, n0, Lc, acc);

    const int lane = threadIdx.x & 31, warp = threadIdx.x >> 5;
    const int wr = warp >> 2, wc = warp & 3, gp = lane >> 2, tg = lane & 3;

    #pragma unroll
    for (int mi = 0; mi < 4; mi++)
        #pragma unroll
        for (int nj = 0; nj < 4; nj++)
            #pragma unroll
            for (int e = 0; e < 4; e++) {
                const int m = m0 + wr * 64 + mi * 16 + gp + ((e >> 1) << 3);
                const int n = n0 + wc * 32 + nj * 8 + 2 * tg + (e & 1);
                const size_t row = (size_t)b * SEQ + m;
                const size_t idx = row * INTER + n;
                const float ctx = acc[mi][nj][e] * g_invZ[row];
                g_g[idx] = __float2half_rn(__half2float(g_u[idx]) * ctx);
            }
}

// ---------------- kernel 5: out = g @ Wo + bo --------------------------------
__global__ __launch_bounds__(256, 2) void k_out(const float* __restrict__ bo,
                                                float* __restrict__ out) {
    float acc[4][4][4] = {};
    const int m0 = blockIdx.y * BM;
    const int n0 = blockIdx.x * BN;
    gemm_f16<true>(g_g, g_wo, INTER, HIDDEN, m0, n0, INTER, acc);

    const int lane = threadIdx.x & 31, warp = threadIdx.x >> 5;
    const int wr = warp >> 2, wc = warp & 3, gp = lane >> 2, tg = lane & 3;

    #pragma unroll
    for (int mi = 0; mi < 4; mi++)
        #pragma unroll
        for (int nj = 0; nj < 4; nj++)
            #pragma unroll
            for (int e = 0; e < 4; e++) {
                const int m = m0 + wr * 64 + mi * 16 + gp + ((e >> 1) << 3);
                const int n = n0 + wc * 32 + nj * 8 + 2 * tg + (e & 1);
                out[(size_t)m * HIDDEN + n] = acc[mi][nj][e] + bo[n];
            }
}

// ---------------- launch ------------------------------------------------------
extern "C" void kernel_launch(void* const* d_in, const int* in_sizes, int n_in,
                              void* d_out, int out_size) {
    const float* hs    = (const float*)d_in[0];
    const int*   mask  = (const int*)  d_in[1];
    // d_in[2] = position_ids (unused)
    const float* Wi    = (const float*)d_in[3];
    const float* bi    = (const float*)d_in[4];
    const float* gamma = (const float*)d_in[5];
    const float* beta  = (const float*)d_in[6];
    const float* Wo    = (const float*)d_in[7];
    const float* bo    = (const float*)d_in[8];
    float* out = (float*)d_out;

    __half *p_hs, *p_wi, *p_wo;
    cudaGetSymbolAddress((void**)&p_hs, g_hs);
    cudaGetSymbolAddress((void**)&p_wi, g_wi);
    cudaGetSymbolAddress((void**)&p_wo, g_wo);

    cudaFuncSetAttribute(k_gemm1,  cudaFuncAttributeMaxDynamicSharedMemorySize, SMEM_BYTES);
    cudaFuncSetAttribute(k_scores, cudaFuncAttributeMaxDynamicSharedMemorySize, SMEM_BYTES);
    cudaFuncSetAttribute(k_ctx,    cudaFuncAttributeMaxDynamicSharedMemorySize, SMEM_BYTES);
    cudaFuncSetAttribute(k_out,    cudaFuncAttributeMaxDynamicSharedMemorySize, SMEM_BYTES);

    dim3 blk(256);
    {   // hs -> half
        const int n4 = M_TOT * HIDDEN / 4;
        k_round_h<<<(n4 + 255) / 256, blk>>>((const float4*)hs, p_hs, n4);
    }
    {   // Wi -> half
        const int n4 = HIDDEN * N1 / 4;
        k_round_h<<<(n4 + 255) / 256, blk>>>((const float4*)Wi, p_wi, n4);
    }
    {   // Wo -> half
        const int n4 = INTER * HIDDEN / 4;
        k_round_h<<<(n4 + 255) / 256, blk>>>((const float4*)Wo, p_wo, n4);
    }
    k_compact<<<dim3(BDIM), blk>>>(mask);

    k_gemm1<<<dim3(N1 / BN, M_TOT / BM), blk, SMEM_BYTES>>>(bi, gamma, beta);
    k_gather<<<dim3(SEQ, BDIM), blk>>>();
    k_scores<<<dim3(SEQ / BN, SEQ / BM, BDIM), blk, SMEM_BYTES>>>();
    k_sum<<<dim3(M_TOT), blk>>>();
    k_ctx<<<dim3(INTER / BN, SEQ / BM, BDIM), blk, SMEM_BYTES>>>();
    k_out<<<dim3(HIDDEN / BN, M_TOT / BM), blk, SMEM_BYTES>>>(bo, out);
}